// round 5
// baseline (speedup 1.0000x reference)
#include <cuda_runtime.h>

#define NN 100000
#define NE 1600000
#define NG 2048

// Scratch (device globals; referenced only from device code)
__device__ float g_A[NN * 256];      // GEMM output
__device__ float g_B[NN * 256];      // gather output / next-layer input
__device__ float g_dinv[NN];
__device__ int   g_deg[NN];
__device__ int   g_rowptr[NN + 1];
__device__ int   g_cursor[NN];
__device__ int   g_esrc[NE];
__device__ int   g_src[NE];
__device__ int   g_dst[NE];
__device__ int   g_batch[NN];
__device__ int   g_is64;
__device__ float g_pool[NG * 256];
__device__ float g_cnt[NG];

// ---------- dtype detection: int64 edge_index has zero high words ----------
__global__ void k_detect(const int* __restrict__ ei32) {
    __shared__ int nz;
    if (threadIdx.x == 0) nz = 0;
    __syncthreads();
    for (int i = threadIdx.x; i < 4096; i += 256)
        if (ei32[2 * i + 1] != 0) atomicAdd(&nz, 1);
    __syncthreads();
    if (threadIdx.x == 0) g_is64 = (nz == 0) ? 1 : 0;
}

__global__ void k_cvt_edges(const void* __restrict__ ei) {
    int e = blockIdx.x * blockDim.x + threadIdx.x;
    if (e >= NE) return;
    if (g_is64) {
        const long long* p = (const long long*)ei;
        g_src[e] = (int)p[e];
        g_dst[e] = (int)p[e + NE];
    } else {
        const int* p = (const int*)ei;
        g_src[e] = p[e];
        g_dst[e] = p[e + NE];
    }
}
__global__ void k_cvt_batch(const void* __restrict__ b) {
    int i = blockIdx.x * blockDim.x + threadIdx.x;
    if (i >= NN) return;
    g_batch[i] = g_is64 ? (int)((const long long*)b)[i] : ((const int*)b)[i];
}

// ---------- degree ----------
__global__ void k_deg_zero() {
    int i = blockIdx.x * blockDim.x + threadIdx.x;
    if (i < NN) g_deg[i] = 0;
}
__global__ void k_deg_count() {
    int e = blockIdx.x * blockDim.x + threadIdx.x;
    if (e < NE) atomicAdd(&g_deg[g_dst[e]], 1);
}
__global__ void k_dinv() {
    int i = blockIdx.x * blockDim.x + threadIdx.x;
    if (i < NN) g_dinv[i] = rsqrtf((float)(g_deg[i] + 1));  // +1 self-loop
}

// ---------- single-block prefix scan over degrees -> rowptr, cursor ----------
__global__ void k_scan() {
    __shared__ int s_data[1024];
    __shared__ int s_off;
    if (threadIdx.x == 0) s_off = 0;
    __syncthreads();
    for (int base = 0; base < NN; base += 1024) {
        int i = base + threadIdx.x;
        int v = (i < NN) ? g_deg[i] : 0;
        s_data[threadIdx.x] = v;
        __syncthreads();
        for (int o = 1; o < 1024; o <<= 1) {
            int t = (threadIdx.x >= o) ? s_data[threadIdx.x - o] : 0;
            __syncthreads();
            s_data[threadIdx.x] += t;
            __syncthreads();
        }
        if (i < NN) {
            int ex = s_off + s_data[threadIdx.x] - v;  // exclusive
            g_rowptr[i] = ex;
            g_cursor[i] = ex;
        }
        __syncthreads();
        if (threadIdx.x == 1023) s_off += s_data[1023];
        __syncthreads();
    }
    if (threadIdx.x == 0) g_rowptr[NN] = s_off;
}

// ---------- bucket edges by dst ----------
__global__ void k_bucket() {
    int e = blockIdx.x * blockDim.x + threadIdx.x;
    if (e >= NE) return;
    int pos = atomicAdd(&g_cursor[g_dst[e]], 1);
    g_esrc[pos] = g_src[e];
}

// ---------- GEMM: g_A[NN,256] = In[NN,K] @ W[K,256] ----------
__global__ void k_gemm(const float* __restrict__ x, int use_gB,
                       const float* __restrict__ W, int K) {
    const float* A = use_gB ? (const float*)g_B : x;
    __shared__ float As[16][65];
    __shared__ float Bs[16][65];
    const int bm = blockIdx.y * 64;
    const int bn = blockIdx.x * 64;
    const int tid = threadIdx.x;
    const int ty = tid >> 4, tx = tid & 15;

    float acc[4][4];
#pragma unroll
    for (int i = 0; i < 4; i++)
#pragma unroll
        for (int j = 0; j < 4; j++) acc[i][j] = 0.0f;

    for (int k0 = 0; k0 < K; k0 += 16) {
#pragma unroll
        for (int p = 0; p < 4; p++) {
            int lr = (tid >> 4) + p * 16;
            int lc = tid & 15;
            int row = bm + lr;
            As[lc][lr] = (row < NN) ? A[(size_t)row * K + k0 + lc] : 0.0f;
        }
#pragma unroll
        for (int p = 0; p < 4; p++) {
            int lr = (tid >> 6) + p * 4;
            int lc = tid & 63;
            Bs[lr][lc] = W[(size_t)(k0 + lr) * 256 + bn + lc];
        }
        __syncthreads();
#pragma unroll
        for (int kk = 0; kk < 16; kk++) {
            float a[4], b[4];
#pragma unroll
            for (int i = 0; i < 4; i++) a[i] = As[kk][ty * 4 + i];
#pragma unroll
            for (int j = 0; j < 4; j++) b[j] = Bs[kk][tx * 4 + j];
#pragma unroll
            for (int i = 0; i < 4; i++)
#pragma unroll
                for (int j = 0; j < 4; j++) acc[i][j] = fmaf(a[i], b[j], acc[i][j]);
        }
        __syncthreads();
    }
#pragma unroll
    for (int i = 0; i < 4; i++) {
        int row = bm + ty * 4 + i;
        if (row < NN) {
#pragma unroll
            for (int j = 0; j < 4; j++)
                g_A[(size_t)row * 256 + bn + tx * 4 + j] = acc[i][j];
        }
    }
}

// ---------- CSR gather + self-loop + bias + relu: g_B = relu(agg(g_A)+b) ----------
__global__ void k_gather(const float* __restrict__ bias) {
    int node = blockIdx.x * 8 + (threadIdx.x >> 5);
    if (node >= NN) return;
    int lane = threadIdx.x & 31;

    float dd = g_dinv[node];
    const float4* hp = (const float4*)g_A;

    float sn = dd * dd;
    float4 a0 = hp[(size_t)node * 64 + lane];
    float4 a1 = hp[(size_t)node * 64 + 32 + lane];
    a0.x *= sn; a0.y *= sn; a0.z *= sn; a0.w *= sn;
    a1.x *= sn; a1.y *= sn; a1.z *= sn; a1.w *= sn;

    int beg = g_rowptr[node];
    int end = g_rowptr[node + 1];
    for (int i = beg; i < end; i++) {
        int s = g_esrc[i];
        float norm = g_dinv[s] * dd;
        float4 v0 = hp[(size_t)s * 64 + lane];
        float4 v1 = hp[(size_t)s * 64 + 32 + lane];
        a0.x = fmaf(v0.x, norm, a0.x);
        a0.y = fmaf(v0.y, norm, a0.y);
        a0.z = fmaf(v0.z, norm, a0.z);
        a0.w = fmaf(v0.w, norm, a0.w);
        a1.x = fmaf(v1.x, norm, a1.x);
        a1.y = fmaf(v1.y, norm, a1.y);
        a1.z = fmaf(v1.z, norm, a1.z);
        a1.w = fmaf(v1.w, norm, a1.w);
    }

    float b0x = bias[lane * 4 + 0], b0y = bias[lane * 4 + 1];
    float b0z = bias[lane * 4 + 2], b0w = bias[lane * 4 + 3];
    float b1x = bias[128 + lane * 4 + 0], b1y = bias[128 + lane * 4 + 1];
    float b1z = bias[128 + lane * 4 + 2], b1w = bias[128 + lane * 4 + 3];
    a0.x = fmaxf(a0.x + b0x, 0.0f);
    a0.y = fmaxf(a0.y + b0y, 0.0f);
    a0.z = fmaxf(a0.z + b0z, 0.0f);
    a0.w = fmaxf(a0.w + b0w, 0.0f);
    a1.x = fmaxf(a1.x + b1x, 0.0f);
    a1.y = fmaxf(a1.y + b1y, 0.0f);
    a1.z = fmaxf(a1.z + b1z, 0.0f);
    a1.w = fmaxf(a1.w + b1w, 0.0f);

    float4* op = (float4*)g_B;
    op[(size_t)node * 64 + lane] = a0;
    op[(size_t)node * 64 + 32 + lane] = a1;
}

// ---------- pool ----------
__global__ void k_pool_zero() {
    int i = blockIdx.x * blockDim.x + threadIdx.x;
    if (i < NG * 256) g_pool[i] = 0.0f;
    if (i < NG) g_cnt[i] = 0.0f;
}
__global__ void k_pool_acc() {
    int node = blockIdx.x * 8 + (threadIdx.x >> 5);
    if (node >= NN) return;
    int lane = threadIdx.x & 31;
    int g = g_batch[node];
    const float4* hp = (const float4*)(g_B + (size_t)node * 256);
    float* pp = g_pool + (size_t)g * 256;

    float4 v0 = hp[lane];
    atomicAdd(pp + lane * 4 + 0, v0.x);
    atomicAdd(pp + lane * 4 + 1, v0.y);
    atomicAdd(pp + lane * 4 + 2, v0.z);
    atomicAdd(pp + lane * 4 + 3, v0.w);
    float4 v1 = hp[lane + 32];
    atomicAdd(pp + 128 + lane * 4 + 0, v1.x);
    atomicAdd(pp + 128 + lane * 4 + 1, v1.y);
    atomicAdd(pp + 128 + lane * 4 + 2, v1.z);
    atomicAdd(pp + 128 + lane * 4 + 3, v1.w);
    if (lane == 0) atomicAdd(&g_cnt[g], 1.0f);
}

// ---------- classifier: mean + GEMV + log_softmax ----------
__global__ void k_classifier(const float* __restrict__ Wc, const float* __restrict__ bc,
                             float* __restrict__ out) {
    int g = blockIdx.x;
    int t = threadIdx.x;  // 0..63
    __shared__ float sm[256];
    __shared__ float wr[2];
    float inv = 1.0f / fmaxf(g_cnt[g], 1.0f);
    for (int k = t; k < 256; k += 64) sm[k] = g_pool[g * 256 + k] * inv;
    __syncthreads();
    float acc = bc[t];
#pragma unroll 8
    for (int k = 0; k < 256; k++) acc = fmaf(sm[k], Wc[k * 64 + t], acc);
    float m = acc;
#pragma unroll
    for (int o = 16; o > 0; o >>= 1) m = fmaxf(m, __shfl_xor_sync(0xffffffffu, m, o));
    if ((t & 31) == 0) wr[t >> 5] = m;
    __syncthreads();
    m = fmaxf(wr[0], wr[1]);
    __syncthreads();
    float e = expf(acc - m);
    float s = e;
#pragma unroll
    for (int o = 16; o > 0; o >>= 1) s += __shfl_xor_sync(0xffffffffu, s, o);
    if ((t & 31) == 0) wr[t >> 5] = s;
    __syncthreads();
    float lse = logf(wr[0] + wr[1]);
    out[g * 64 + t] = acc - m - lse;
}

extern "C" void kernel_launch(void* const* d_in, const int* in_sizes, int n_in,
                              void* d_out, int out_size) {
    const float* x    = (const float*)d_in[0];
    const void*  ei   = d_in[1];
    const void*  batch= d_in[2];
    const float* W1   = (const float*)d_in[3];
    const float* b1   = (const float*)d_in[4];
    const float* W2   = (const float*)d_in[5];
    const float* b2   = (const float*)d_in[6];
    const float* Wc   = (const float*)d_in[7];
    const float* bc   = (const float*)d_in[8];
    float* out = (float*)d_out;

    // dtype detect + canonicalize indices to int32
    k_detect<<<1, 256>>>((const int*)ei);
    k_cvt_edges<<<(NE + 255) / 256, 256>>>(ei);
    k_cvt_batch<<<(NN + 255) / 256, 256>>>(batch);

    // CSR build
    k_deg_zero<<<(NN + 255) / 256, 256>>>();
    k_deg_count<<<(NE + 255) / 256, 256>>>();
    k_dinv<<<(NN + 255) / 256, 256>>>();
    k_scan<<<1, 1024>>>();
    k_bucket<<<(NE + 255) / 256, 256>>>();

    dim3 ggrid(4, (NN + 63) / 64);
    // layer 1: g_A = x @ W1 ; g_B = relu(agg(g_A) + b1)
    k_gemm<<<ggrid, 256>>>(x, 0, W1, 128);
    k_gather<<<(NN + 7) / 8, 256>>>(b1);
    // layer 2: g_A = g_B @ W2 ; g_B = relu(agg(g_A) + b2)
    k_gemm<<<ggrid, 256>>>(x, 1, W2, 256);
    k_gather<<<(NN + 7) / 8, 256>>>(b2);

    // pool + classifier
    k_pool_zero<<<(NG * 256 + 255) / 256, 256>>>();
    k_pool_acc<<<(NN + 7) / 8, 256>>>();
    k_classifier<<<NG, 64>>>(Wc, bc, out);
}

// round 7
// speedup vs baseline: 1.7094x; 1.7094x over previous
#include <cuda_runtime.h>

#define NN 100000
#define NE 1600000
#define NG 2048
#define NBLK 98   // ceil(NN/1024)

// Scratch (device globals; referenced only from device code)
__device__ float g_A[NN * 256];      // gather output (GEMM input)
__device__ float g_B[NN * 256];      // GEMM output (gather/pool input)
__device__ float g_dinv[NN];
__device__ int   g_deg[NN];
__device__ int   g_rowptr[NN + 1];
__device__ int   g_cursor[NN];
__device__ int   g_esrc[NE];
__device__ int   g_src[NE];
__device__ int   g_dst[NE];
__device__ int   g_batch[NN];
__device__ int   g_bsum[NBLK];
__device__ int   g_is64;
__device__ float g_pool[NG * 256];

// ---------- dtype detection: int64 edge_index has zero high words ----------
__global__ void k_detect(const int* __restrict__ ei32) {
    __shared__ int nz;
    if (threadIdx.x == 0) nz = 0;
    __syncthreads();
    for (int i = threadIdx.x; i < 4096; i += 256)
        if (ei32[2 * i + 1] != 0) atomicAdd(&nz, 1);
    __syncthreads();
    if (threadIdx.x == 0) g_is64 = (nz == 0) ? 1 : 0;
}

__global__ void k_cvt_edges(const void* __restrict__ ei) {
    int e = blockIdx.x * blockDim.x + threadIdx.x;
    if (e >= NE) return;
    if (g_is64) {
        const long long* p = (const long long*)ei;
        g_src[e] = (int)p[e];
        g_dst[e] = (int)p[e + NE];
    } else {
        const int* p = (const int*)ei;
        g_src[e] = p[e];
        g_dst[e] = p[e + NE];
    }
}
__global__ void k_cvt_batch(const void* __restrict__ b) {
    int i = blockIdx.x * blockDim.x + threadIdx.x;
    if (i >= NN) return;
    g_batch[i] = g_is64 ? (int)((const long long*)b)[i] : ((const int*)b)[i];
}

// ---------- degree ----------
__global__ void k_deg_zero() {
    int i = blockIdx.x * blockDim.x + threadIdx.x;
    if (i < NN) g_deg[i] = 0;
}
__global__ void k_deg_count() {
    int e = blockIdx.x * blockDim.x + threadIdx.x;
    if (e < NE) atomicAdd(&g_deg[g_dst[e]], 1);
}
__global__ void k_dinv() {
    int i = blockIdx.x * blockDim.x + threadIdx.x;
    if (i < NN) g_dinv[i] = rsqrtf((float)(g_deg[i] + 1));  // +1 self-loop
}

// ---------- multi-block exclusive scan of degrees -> rowptr, cursor ----------
__global__ void k_scan1() {
    int t = threadIdx.x;
    int i = blockIdx.x * 1024 + t;
    int v = (i < NN) ? g_deg[i] : 0;
    int lane = t & 31, wid = t >> 5;
    int x = v;
#pragma unroll
    for (int o = 1; o < 32; o <<= 1) {
        int y = __shfl_up_sync(0xffffffffu, x, o);
        if (lane >= o) x += y;
    }
    __shared__ int wsum[32];
    if (lane == 31) wsum[wid] = x;
    __syncthreads();
    if (wid == 0) {
        int s = wsum[lane];
#pragma unroll
        for (int o = 1; o < 32; o <<= 1) {
            int y = __shfl_up_sync(0xffffffffu, s, o);
            if (lane >= o) s += y;
        }
        wsum[lane] = s;
    }
    __syncthreads();
    int incl = x + (wid > 0 ? wsum[wid - 1] : 0);
    if (i < NN) g_rowptr[i] = incl - v;      // block-local exclusive
    if (t == 1023) g_bsum[blockIdx.x] = incl; // block total (warp31 inclusive end)
}
__global__ void k_scan2() {
    if (threadIdx.x == 0) {
        int acc = 0;
        for (int b = 0; b < NBLK; b++) { int v = g_bsum[b]; g_bsum[b] = acc; acc += v; }
        g_rowptr[NN] = acc;
    }
}
__global__ void k_scan3() {
    int i = blockIdx.x * blockDim.x + threadIdx.x;
    if (i < NN) {
        int r = g_rowptr[i] + g_bsum[i >> 10];
        g_rowptr[i] = r;
        g_cursor[i] = r;
    }
}

// ---------- bucket edges by dst ----------
__global__ void k_bucket() {
    int e = blockIdx.x * blockDim.x + threadIdx.x;
    if (e >= NE) return;
    int pos = atomicAdd(&g_cursor[g_dst[e]], 1);
    g_esrc[pos] = g_src[e];
}

// ---------- gather (128-wide): g_A[:,0:128] = agg(x). warp per node ----------
__global__ void k_gather128(const float* __restrict__ x) {
    int node = blockIdx.x * 8 + (threadIdx.x >> 5);
    if (node >= NN) return;
    int lane = threadIdx.x & 31;
    float dd = g_dinv[node];
    const float4* hp = (const float4*)x;

    float sn = dd * dd;
    float4 a = hp[(size_t)node * 32 + lane];
    a.x *= sn; a.y *= sn; a.z *= sn; a.w *= sn;

    int beg = g_rowptr[node], end = g_rowptr[node + 1];
#pragma unroll 4
    for (int i = beg; i < end; i++) {
        int s = g_esrc[i];
        float norm = g_dinv[s] * dd;
        float4 v = hp[(size_t)s * 32 + lane];
        a.x = fmaf(v.x, norm, a.x);
        a.y = fmaf(v.y, norm, a.y);
        a.z = fmaf(v.z, norm, a.z);
        a.w = fmaf(v.w, norm, a.w);
    }
    ((float4*)g_A)[(size_t)node * 32 + lane] = a;
}

// ---------- gather (256-wide): g_A = agg(g_B). warp per node ----------
__global__ void k_gather256() {
    int node = blockIdx.x * 8 + (threadIdx.x >> 5);
    if (node >= NN) return;
    int lane = threadIdx.x & 31;
    float dd = g_dinv[node];
    const float4* hp = (const float4*)g_B;

    float sn = dd * dd;
    float4 a0 = hp[(size_t)node * 64 + lane];
    float4 a1 = hp[(size_t)node * 64 + 32 + lane];
    a0.x *= sn; a0.y *= sn; a0.z *= sn; a0.w *= sn;
    a1.x *= sn; a1.y *= sn; a1.z *= sn; a1.w *= sn;

    int beg = g_rowptr[node], end = g_rowptr[node + 1];
#pragma unroll 2
    for (int i = beg; i < end; i++) {
        int s = g_esrc[i];
        float norm = g_dinv[s] * dd;
        float4 v0 = hp[(size_t)s * 64 + lane];
        float4 v1 = hp[(size_t)s * 64 + 32 + lane];
        a0.x = fmaf(v0.x, norm, a0.x);
        a0.y = fmaf(v0.y, norm, a0.y);
        a0.z = fmaf(v0.z, norm, a0.z);
        a0.w = fmaf(v0.w, norm, a0.w);
        a1.x = fmaf(v1.x, norm, a1.x);
        a1.y = fmaf(v1.y, norm, a1.y);
        a1.z = fmaf(v1.z, norm, a1.z);
        a1.w = fmaf(v1.w, norm, a1.w);
    }
    ((float4*)g_A)[(size_t)node * 64 + lane] = a0;
    ((float4*)g_A)[(size_t)node * 64 + 32 + lane] = a1;
}

// ---------- GEMM + bias + relu: g_B[NN,256] = relu(g_A[NN,K] @ W + b) ----------
// 128x128 tile, BK=16, 256 threads, 8x8 per thread (split 4+4)
__global__ void __launch_bounds__(256) k_gemm_br(const float* __restrict__ W,
                                                 const float* __restrict__ bias, int K) {
    __shared__ float As[16][128];
    __shared__ float Bs[16][128];
    const int bm = blockIdx.y * 128;
    const int bn = blockIdx.x * 128;
    const int tid = threadIdx.x;
    const int tx = tid & 15, ty = tid >> 4;
    const int K4 = K >> 2;

    float acc[8][8];
#pragma unroll
    for (int i = 0; i < 8; i++)
#pragma unroll
        for (int j = 0; j < 8; j++) acc[i][j] = 0.0f;

    for (int k0 = 0; k0 < K; k0 += 16) {
        // A tile: 128 rows x 16 cols = 512 float4
#pragma unroll
        for (int p = 0; p < 2; p++) {
            int idx = tid + p * 256;
            int row = idx >> 2, c4 = idx & 3;
            int gr = bm + row;
            float4 v = make_float4(0.f, 0.f, 0.f, 0.f);
            if (gr < NN) v = ((const float4*)g_A)[(size_t)gr * K4 + (k0 >> 2) + c4];
            As[c4 * 4 + 0][row] = v.x;
            As[c4 * 4 + 1][row] = v.y;
            As[c4 * 4 + 2][row] = v.z;
            As[c4 * 4 + 3][row] = v.w;
        }
        // W tile: 16 rows x 128 cols = 512 float4
#pragma unroll
        for (int p = 0; p < 2; p++) {
            int idx = tid + p * 256;
            int row = idx >> 5, c4 = idx & 31;
            float4 v = *(const float4*)&W[(size_t)(k0 + row) * 256 + bn + c4 * 4];
            *(float4*)&Bs[row][c4 * 4] = v;
        }
        __syncthreads();
#pragma unroll
        for (int kk = 0; kk < 16; kk++) {
            float4 a0 = *(float4*)&As[kk][ty * 4];
            float4 a1 = *(float4*)&As[kk][64 + ty * 4];
            float4 b0 = *(float4*)&Bs[kk][tx * 4];
            float4 b1 = *(float4*)&Bs[kk][64 + tx * 4];
            float a[8] = {a0.x, a0.y, a0.z, a0.w, a1.x, a1.y, a1.z, a1.w};
            float b[8] = {b0.x, b0.y, b0.z, b0.w, b1.x, b1.y, b1.z, b1.w};
#pragma unroll
            for (int i = 0; i < 8; i++)
#pragma unroll
                for (int j = 0; j < 8; j++) acc[i][j] = fmaf(a[i], b[j], acc[i][j]);
        }
        __syncthreads();
    }
    // epilogue: bias + relu
    float4 bb0 = *(const float4*)&bias[bn + tx * 4];
    float4 bb1 = *(const float4*)&bias[bn + 64 + tx * 4];
#pragma unroll
    for (int ih = 0; ih < 2; ih++) {
#pragma unroll
        for (int i = 0; i < 4; i++) {
            int gr = bm + ih * 64 + ty * 4 + i;
            if (gr >= NN) continue;
            int ai = ih * 4 + i;
            float4 o0, o1;
            o0.x = fmaxf(acc[ai][0] + bb0.x, 0.0f);
            o0.y = fmaxf(acc[ai][1] + bb0.y, 0.0f);
            o0.z = fmaxf(acc[ai][2] + bb0.z, 0.0f);
            o0.w = fmaxf(acc[ai][3] + bb0.w, 0.0f);
            o1.x = fmaxf(acc[ai][4] + bb1.x, 0.0f);
            o1.y = fmaxf(acc[ai][5] + bb1.y, 0.0f);
            o1.z = fmaxf(acc[ai][6] + bb1.z, 0.0f);
            o1.w = fmaxf(acc[ai][7] + bb1.w, 0.0f);
            *(float4*)&g_B[(size_t)gr * 256 + bn + tx * 4] = o0;
            *(float4*)&g_B[(size_t)gr * 256 + bn + 64 + tx * 4] = o1;
        }
    }
}

// ---------- pool: block per graph, batch is sorted -> binary search range ----------
__global__ void k_pool() {
    int g = blockIdx.x;
    __shared__ int sbeg, send;
    if (threadIdx.x == 0) {
        int lo = 0, hi = NN;
        while (lo < hi) { int mid = (lo + hi) >> 1; if (g_batch[mid] < g) lo = mid + 1; else hi = mid; }
        sbeg = lo;
        hi = NN;
        while (lo < hi) { int mid = (lo + hi) >> 1; if (g_batch[mid] < g + 1) lo = mid + 1; else hi = mid; }
        send = lo;
    }
    __syncthreads();
    int beg = sbeg, end = send;
    float acc = 0.0f;
    for (int n = beg; n < end; n++) acc += g_B[(size_t)n * 256 + threadIdx.x];
    float inv = (end > beg) ? 1.0f / (float)(end - beg) : 1.0f;
    g_pool[(size_t)g * 256 + threadIdx.x] = acc * inv;   // mean
}

// ---------- classifier: GEMV + log_softmax ----------
__global__ void k_classifier(const float* __restrict__ Wc, const float* __restrict__ bc,
                             float* __restrict__ out) {
    int g = blockIdx.x;
    int t = threadIdx.x;  // 0..63
    __shared__ float sm[256];
    __shared__ float wr[2];
    for (int k = t; k < 256; k += 64) sm[k] = g_pool[(size_t)g * 256 + k];
    __syncthreads();
    float acc = bc[t];
#pragma unroll 8
    for (int k = 0; k < 256; k++) acc = fmaf(sm[k], Wc[k * 64 + t], acc);
    float m = acc;
#pragma unroll
    for (int o = 16; o > 0; o >>= 1) m = fmaxf(m, __shfl_xor_sync(0xffffffffu, m, o));
    if ((t & 31) == 0) wr[t >> 5] = m;
    __syncthreads();
    m = fmaxf(wr[0], wr[1]);
    __syncthreads();
    float e = expf(acc - m);
    float s = e;
#pragma unroll
    for (int o = 16; o > 0; o >>= 1) s += __shfl_xor_sync(0xffffffffu, s, o);
    if ((t & 31) == 0) wr[t >> 5] = s;
    __syncthreads();
    float lse = logf(wr[0] + wr[1]);
    out[g * 64 + t] = acc - m - lse;
}

extern "C" void kernel_launch(void* const* d_in, const int* in_sizes, int n_in,
                              void* d_out, int out_size) {
    const float* x    = (const float*)d_in[0];
    const void*  ei   = d_in[1];
    const void*  batch= d_in[2];
    const float* W1   = (const float*)d_in[3];
    const float* b1   = (const float*)d_in[4];
    const float* W2   = (const float*)d_in[5];
    const float* b2   = (const float*)d_in[6];
    const float* Wc   = (const float*)d_in[7];
    const float* bc   = (const float*)d_in[8];
    float* out = (float*)d_out;

    // dtype detect + canonicalize indices to int32
    k_detect<<<1, 256>>>((const int*)ei);
    k_cvt_edges<<<(NE + 255) / 256, 256>>>(ei);
    k_cvt_batch<<<(NN + 255) / 256, 256>>>(batch);

    // CSR build
    k_deg_zero<<<(NN + 255) / 256, 256>>>();
    k_deg_count<<<(NE + 255) / 256, 256>>>();
    k_dinv<<<(NN + 255) / 256, 256>>>();
    k_scan1<<<NBLK, 1024>>>();
    k_scan2<<<1, 32>>>();
    k_scan3<<<(NN + 255) / 256, 256>>>();
    k_bucket<<<(NE + 255) / 256, 256>>>();

    dim3 ggrid(2, (NN + 127) / 128);
    // layer 1: g_A = agg(x); g_B = relu(g_A @ W1 + b1)
    k_gather128<<<(NN + 7) / 8, 256>>>(x);
    k_gemm_br<<<ggrid, 256>>>(W1, b1, 128);
    // layer 2: g_A = agg(g_B); g_B = relu(g_A @ W2 + b2)
    k_gather256<<<(NN + 7) / 8, 256>>>();
    k_gemm_br<<<ggrid, 256>>>(W2, b2, 256);

    // pool (mean, no atomics) + classifier
    k_pool<<<NG, 256>>>();
    k_classifier<<<NG, 64>>>(Wc, bc, out);
}

// round 11
// speedup vs baseline: 1.9668x; 1.1505x over previous
#include <cuda_runtime.h>
#include <cuda_bf16.h>
#include <cstdint>

#define NN 100000
#define NE 1600000
#define NG 2048
#define NBLK 98   // ceil(NN/1024)

// ---------------- device scratch (NEVER referenced from host code) ----------------
__device__ float g_A[NN * 256];      // gather output (GEMM input)
__device__ float g_B[NN * 256];      // GEMM output (gather/pool input)
__device__ float g_dinv[NN];
__device__ int   g_deg[NN];
__device__ int   g_rowptr[NN + 1];
__device__ int   g_cursor[NN];
__device__ int   g_esrc[NE];
__device__ int   g_src[NE];
__device__ int   g_dst[NE];
__device__ int   g_batch[NN];
__device__ int   g_bsum[NBLK];
__device__ int   g_is64;
__device__ float g_pool[NG * 256];

// ---------------- dtype detection + conversion ----------------
__global__ void k_detect(const int* __restrict__ ei32) {
    __shared__ int nz;
    if (threadIdx.x == 0) nz = 0;
    __syncthreads();
    for (int i = threadIdx.x; i < 4096; i += 256)
        if (ei32[2 * i + 1] != 0) atomicAdd(&nz, 1);
    __syncthreads();
    if (threadIdx.x == 0) g_is64 = (nz == 0) ? 1 : 0;
}
__global__ void k_cvt_edges(const void* __restrict__ ei) {
    int e = blockIdx.x * blockDim.x + threadIdx.x;
    if (e >= NE) return;
    if (g_is64) {
        const long long* p = (const long long*)ei;
        g_src[e] = (int)p[e];
        g_dst[e] = (int)p[e + NE];
    } else {
        const int* p = (const int*)ei;
        g_src[e] = p[e];
        g_dst[e] = p[e + NE];
    }
}
__global__ void k_cvt_batch(const void* __restrict__ b) {
    int i = blockIdx.x * blockDim.x + threadIdx.x;
    if (i >= NN) return;
    g_batch[i] = g_is64 ? (int)((const long long*)b)[i] : ((const int*)b)[i];
}

// ---------------- degree + CSR ----------------
__global__ void k_deg_zero() {
    int i = blockIdx.x * blockDim.x + threadIdx.x;
    if (i < NN) g_deg[i] = 0;
}
__global__ void k_deg_count() {
    int e = blockIdx.x * blockDim.x + threadIdx.x;
    if (e < NE) atomicAdd(&g_deg[g_dst[e]], 1);
}
__global__ void k_dinv() {
    int i = blockIdx.x * blockDim.x + threadIdx.x;
    if (i < NN) g_dinv[i] = rsqrtf((float)(g_deg[i] + 1));
}
__global__ void k_scan1() {
    int t = threadIdx.x;
    int i = blockIdx.x * 1024 + t;
    int v = (i < NN) ? g_deg[i] : 0;
    int lane = t & 31, wid = t >> 5;
    int x = v;
#pragma unroll
    for (int o = 1; o < 32; o <<= 1) {
        int y = __shfl_up_sync(0xffffffffu, x, o);
        if (lane >= o) x += y;
    }
    __shared__ int wsum[32];
    if (lane == 31) wsum[wid] = x;
    __syncthreads();
    if (wid == 0) {
        int s = wsum[lane];
#pragma unroll
        for (int o = 1; o < 32; o <<= 1) {
            int y = __shfl_up_sync(0xffffffffu, s, o);
            if (lane >= o) s += y;
        }
        wsum[lane] = s;
    }
    __syncthreads();
    int incl = x + (wid > 0 ? wsum[wid - 1] : 0);
    if (i < NN) g_rowptr[i] = incl - v;
    if (t == 1023) g_bsum[blockIdx.x] = incl;
}
__global__ void k_scan2() {
    if (threadIdx.x == 0) {
        int acc = 0;
        for (int b = 0; b < NBLK; b++) { int v = g_bsum[b]; g_bsum[b] = acc; acc += v; }
        g_rowptr[NN] = acc;
    }
}
__global__ void k_scan3() {
    int i = blockIdx.x * blockDim.x + threadIdx.x;
    if (i < NN) {
        int r = g_rowptr[i] + g_bsum[i >> 10];
        g_rowptr[i] = r;
        g_cursor[i] = r;
    }
}
__global__ void k_bucket() {
    int e = blockIdx.x * blockDim.x + threadIdx.x;
    if (e >= NE) return;
    int pos = atomicAdd(&g_cursor[g_dst[e]], 1);
    g_esrc[pos] = g_src[e];
}

// ---------------- gathers (warp per node) ----------------
__global__ void k_gather128(const float* __restrict__ x) {
    int node = blockIdx.x * 8 + (threadIdx.x >> 5);
    if (node >= NN) return;
    int lane = threadIdx.x & 31;
    float dd = g_dinv[node];
    const float4* hp = (const float4*)x;

    float sn = dd * dd;
    float4 a = hp[(size_t)node * 32 + lane];
    a.x *= sn; a.y *= sn; a.z *= sn; a.w *= sn;

    int beg = g_rowptr[node], end = g_rowptr[node + 1];
#pragma unroll 4
    for (int i = beg; i < end; i++) {
        int s = g_esrc[i];
        float norm = g_dinv[s] * dd;
        float4 v = hp[(size_t)s * 32 + lane];
        a.x = fmaf(v.x, norm, a.x);
        a.y = fmaf(v.y, norm, a.y);
        a.z = fmaf(v.z, norm, a.z);
        a.w = fmaf(v.w, norm, a.w);
    }
    ((float4*)g_A)[(size_t)node * 32 + lane] = a;
}
__global__ void k_gather256() {
    int node = blockIdx.x * 8 + (threadIdx.x >> 5);
    if (node >= NN) return;
    int lane = threadIdx.x & 31;
    float dd = g_dinv[node];
    const float4* hp = (const float4*)g_B;

    float sn = dd * dd;
    float4 a0 = hp[(size_t)node * 64 + lane];
    float4 a1 = hp[(size_t)node * 64 + 32 + lane];
    a0.x *= sn; a0.y *= sn; a0.z *= sn; a0.w *= sn;
    a1.x *= sn; a1.y *= sn; a1.z *= sn; a1.w *= sn;

    int beg = g_rowptr[node], end = g_rowptr[node + 1];
#pragma unroll 2
    for (int i = beg; i < end; i++) {
        int s = g_esrc[i];
        float norm = g_dinv[s] * dd;
        float4 v0 = hp[(size_t)s * 64 + lane];
        float4 v1 = hp[(size_t)s * 64 + 32 + lane];
        a0.x = fmaf(v0.x, norm, a0.x);
        a0.y = fmaf(v0.y, norm, a0.y);
        a0.z = fmaf(v0.z, norm, a0.z);
        a0.w = fmaf(v0.w, norm, a0.w);
        a1.x = fmaf(v1.x, norm, a1.x);
        a1.y = fmaf(v1.y, norm, a1.y);
        a1.z = fmaf(v1.z, norm, a1.z);
        a1.w = fmaf(v1.w, norm, a1.w);
    }
    ((float4*)g_A)[(size_t)node * 64 + lane] = a0;
    ((float4*)g_A)[(size_t)node * 64 + 32 + lane] = a1;
}

// ---------------- explicit mma.sync bf16 hi/lo GEMM ----------------
// g_B = relu(g_A[NN,K] @ W[K,256] + b). CTA 128x128, 8 warps (4m x 2n),
// warp tile 32x64 = 2(m) x 8(n) m16n8k16 tiles. BK=32.
// NOTE: g_A is read DIRECTLY in device code (host-side symbol passing is UB
// and silently reads host shadow memory on GB300 ATS).
#define LDK 36   // padded k leading dim (elements)

#define MMA_BF16(d, a, b0, b1) \
    asm volatile("mma.sync.aligned.m16n8k16.row.col.f32.bf16.bf16.f32 " \
        "{%0,%1,%2,%3}, {%4,%5,%6,%7}, {%8,%9}, {%0,%1,%2,%3};" \
        : "+f"((d)[0]), "+f"((d)[1]), "+f"((d)[2]), "+f"((d)[3]) \
        : "r"((a)[0]), "r"((a)[1]), "r"((a)[2]), "r"((a)[3]), "r"(b0), "r"(b1))

// bit-truncation hi/lo split of two floats -> packed bf16x2 (lo16 = first elem)
__device__ __forceinline__ void split2(float x, float y, uint32_t& hpack, uint32_t& lpack) {
    uint32_t ux = __float_as_uint(x), uy = __float_as_uint(y);
    float hx = __uint_as_float(ux & 0xffff0000u);
    float hy = __uint_as_float(uy & 0xffff0000u);
    hpack = (ux >> 16) | (uy & 0xffff0000u);
    __nv_bfloat162 lo2 = __floats2bfloat162_rn(x - hx, y - hy);  // .x -> low bits
    lpack = *reinterpret_cast<uint32_t*>(&lo2);
}

__global__ void __launch_bounds__(256) k_gemm_mma(const float* __restrict__ W,
                                                  const float* __restrict__ bias, int K) {
    __shared__ __align__(16) unsigned short AH[128 * LDK], AL[128 * LDK];
    __shared__ __align__(16) unsigned short BH[128 * LDK], BL[128 * LDK];

    const int tid = threadIdx.x;
    const int wid = tid >> 5, lane = tid & 31;
    const int g = lane >> 2, t = lane & 3;
    const int wm = (wid & 3) * 32;
    const int wn = (wid >> 2) * 64;
    const int bm = blockIdx.y * 128;
    const int bn = blockIdx.x * 128;

    float acc[2][8][4];
#pragma unroll
    for (int mi = 0; mi < 2; mi++)
#pragma unroll
        for (int ni = 0; ni < 8; ni++)
#pragma unroll
            for (int c = 0; c < 4; c++) acc[mi][ni][c] = 0.0f;

    const int nch = K >> 5;
    for (int ch = 0; ch < nch; ch++) {
        const int k0 = ch << 5;
        // A chunk: 128 rows x 32 k = 2048 float2 pairs (from g_A, device symbol)
#pragma unroll
        for (int it = 0; it < 8; it++) {
            int idx = tid + it * 256;
            int row = idx >> 4, kp = idx & 15;
            int gr = bm + row;
            float2 v = make_float2(0.f, 0.f);
            if (gr < NN) v = *(const float2*)&g_A[(size_t)gr * K + k0 + kp * 2];
            uint32_t hp_, lp_;
            split2(v.x, v.y, hp_, lp_);
            *(uint32_t*)&AH[row * LDK + kp * 2] = hp_;
            *(uint32_t*)&AL[row * LDK + kp * 2] = lp_;
        }
        // B chunk transposed: BT[n][k], n=0..127, k=0..31 (16 k-pairs)
#pragma unroll
        for (int it = 0; it < 8; it++) {
            int idx = tid + it * 256;
            int n = idx & 127, kp = idx >> 7;   // kp in [0,16)
            float wx = W[(size_t)(k0 + kp * 2) * 256 + bn + n];
            float wy = W[(size_t)(k0 + kp * 2 + 1) * 256 + bn + n];
            uint32_t hp_, lp_;
            split2(wx, wy, hp_, lp_);
            *(uint32_t*)&BH[n * LDK + kp * 2] = hp_;
            *(uint32_t*)&BL[n * LDK + kp * 2] = lp_;
        }
        __syncthreads();

#pragma unroll
        for (int ks = 0; ks < 2; ks++) {
            const int c = ks * 16 + t * 2;
            uint32_t ah[2][4], al_[2][4];
#pragma unroll
            for (int mi = 0; mi < 2; mi++) {
                int r = wm + mi * 16 + g;
                ah[mi][0]  = *(uint32_t*)&AH[r * LDK + c];
                ah[mi][1]  = *(uint32_t*)&AH[(r + 8) * LDK + c];
                ah[mi][2]  = *(uint32_t*)&AH[r * LDK + c + 8];
                ah[mi][3]  = *(uint32_t*)&AH[(r + 8) * LDK + c + 8];
                al_[mi][0] = *(uint32_t*)&AL[r * LDK + c];
                al_[mi][1] = *(uint32_t*)&AL[(r + 8) * LDK + c];
                al_[mi][2] = *(uint32_t*)&AL[r * LDK + c + 8];
                al_[mi][3] = *(uint32_t*)&AL[(r + 8) * LDK + c + 8];
            }
#pragma unroll
            for (int ni = 0; ni < 8; ni++) {
                int n = wn + ni * 8 + g;
                uint32_t bh0 = *(uint32_t*)&BH[n * LDK + c];
                uint32_t bh1 = *(uint32_t*)&BH[n * LDK + c + 8];
                uint32_t bl0 = *(uint32_t*)&BL[n * LDK + c];
                uint32_t bl1 = *(uint32_t*)&BL[n * LDK + c + 8];
#pragma unroll
                for (int mi = 0; mi < 2; mi++) {
                    MMA_BF16(acc[mi][ni], ah[mi], bh0, bh1);
                    MMA_BF16(acc[mi][ni], ah[mi], bl0, bl1);
                    MMA_BF16(acc[mi][ni], al_[mi], bh0, bh1);
                }
            }
        }
        __syncthreads();
    }

    // epilogue: bias + relu, direct from accumulators
#pragma unroll
    for (int mi = 0; mi < 2; mi++) {
        int r0 = bm + wm + mi * 16 + g;
        int r1 = r0 + 8;
#pragma unroll
        for (int ni = 0; ni < 8; ni++) {
            int cg = bn + wn + ni * 8 + t * 2;
            float2 bb = *(const float2*)&bias[cg];
            if (r0 < NN) {
                float2 o;
                o.x = fmaxf(acc[mi][ni][0] + bb.x, 0.f);
                o.y = fmaxf(acc[mi][ni][1] + bb.y, 0.f);
                *(float2*)&g_B[(size_t)r0 * 256 + cg] = o;
            }
            if (r1 < NN) {
                float2 o;
                o.x = fmaxf(acc[mi][ni][2] + bb.x, 0.f);
                o.y = fmaxf(acc[mi][ni][3] + bb.y, 0.f);
                *(float2*)&g_B[(size_t)r1 * 256 + cg] = o;
            }
        }
    }
}

// ---------------- pool (batch sorted) + classifier ----------------
__global__ void k_pool() {
    int g = blockIdx.x;
    __shared__ int sbeg, send;
    if (threadIdx.x == 0) {
        int lo = 0, hi = NN;
        while (lo < hi) { int mid = (lo + hi) >> 1; if (g_batch[mid] < g) lo = mid + 1; else hi = mid; }
        sbeg = lo;
        hi = NN;
        while (lo < hi) { int mid = (lo + hi) >> 1; if (g_batch[mid] < g + 1) lo = mid + 1; else hi = mid; }
        send = lo;
    }
    __syncthreads();
    int beg = sbeg, end = send;
    float acc = 0.0f;
    for (int n = beg; n < end; n++) acc += g_B[(size_t)n * 256 + threadIdx.x];
    float inv = (end > beg) ? 1.0f / (float)(end - beg) : 1.0f;
    g_pool[(size_t)g * 256 + threadIdx.x] = acc * inv;
}
__global__ void k_classifier(const float* __restrict__ Wc, const float* __restrict__ bc,
                             float* __restrict__ out) {
    int g = blockIdx.x;
    int t = threadIdx.x;
    __shared__ float sm[256];
    __shared__ float wr_[2];
    for (int k = t; k < 256; k += 64) sm[k] = g_pool[(size_t)g * 256 + k];
    __syncthreads();
    float acc = bc[t];
#pragma unroll 8
    for (int k = 0; k < 256; k++) acc = fmaf(sm[k], Wc[k * 64 + t], acc);
    float m = acc;
#pragma unroll
    for (int o = 16; o > 0; o >>= 1) m = fmaxf(m, __shfl_xor_sync(0xffffffffu, m, o));
    if ((t & 31) == 0) wr_[t >> 5] = m;
    __syncthreads();
    m = fmaxf(wr_[0], wr_[1]);
    __syncthreads();
    float e = expf(acc - m);
    float s = e;
#pragma unroll
    for (int o = 16; o > 0; o >>= 1) s += __shfl_xor_sync(0xffffffffu, s, o);
    if ((t & 31) == 0) wr_[t >> 5] = s;
    __syncthreads();
    float lse = logf(wr_[0] + wr_[1]);
    out[g * 64 + t] = acc - m - lse;
}

extern "C" void kernel_launch(void* const* d_in, const int* in_sizes, int n_in,
                              void* d_out, int out_size) {
    const float* x    = (const float*)d_in[0];
    const void*  ei   = d_in[1];
    const void*  batch= d_in[2];
    const float* W1   = (const float*)d_in[3];
    const float* b1   = (const float*)d_in[4];
    const float* W2   = (const float*)d_in[5];
    const float* b2   = (const float*)d_in[6];
    const float* Wc   = (const float*)d_in[7];
    const float* bc   = (const float*)d_in[8];
    float* out = (float*)d_out;

    k_detect<<<1, 256>>>((const int*)ei);
    k_cvt_edges<<<(NE + 255) / 256, 256>>>(ei);
    k_cvt_batch<<<(NN + 255) / 256, 256>>>(batch);

    k_deg_zero<<<(NN + 255) / 256, 256>>>();
    k_deg_count<<<(NE + 255) / 256, 256>>>();
    k_dinv<<<(NN + 255) / 256, 256>>>();
    k_scan1<<<NBLK, 1024>>>();
    k_scan2<<<1, 32>>>();
    k_scan3<<<(NN + 255) / 256, 256>>>();
    k_bucket<<<(NE + 255) / 256, 256>>>();

    dim3 ggrid(2, (NN + 127) / 128);
    // layer 1: g_A = agg(x); g_B = relu(g_A @ W1 + b1)
    k_gather128<<<(NN + 7) / 8, 256>>>(x);
    k_gemm_mma<<<ggrid, 256>>>(W1, b1, 128);
    // layer 2: g_A = agg(g_B); g_B = relu(g_A @ W2 + b2)
    k_gather256<<<(NN + 7) / 8, 256>>>();
    k_gemm_mma<<<ggrid, 256>>>(W2, b2, 256);

    k_pool<<<NG, 256>>>();
    k_classifier<<<NG, 64>>>(Wc, bc, out);
}